// round 2
// baseline (speedup 1.0000x reference)
#include <cuda_runtime.h>
#include <cstdint>

#define BB 8
#define SS 2048
#define HH 16
#define DD 64
#define DM 1024
#define WW 4
#define SC 512
#define PAD 68
#define PPAD 36

__device__ float g_kc[BB*HH*SC*DD];
__device__ float g_vc[BB*HH*SC*DD];
__device__ float g_ao[BB*SS*DM];

__device__ __forceinline__ unsigned f2tf(float x){
  unsigned u; asm("cvt.rna.tf32.f32 %0, %1;" : "=r"(u) : "f"(x)); return u;
}
__device__ __forceinline__ void mma8(float* c, unsigned a0, unsigned a1, unsigned a2,
                                     unsigned a3, unsigned b0, unsigned b1){
  asm volatile(
    "mma.sync.aligned.m16n8k8.row.col.f32.tf32.tf32.f32 "
    "{%0,%1,%2,%3},{%4,%5,%6,%7},{%8,%9},{%0,%1,%2,%3};"
    : "+f"(c[0]), "+f"(c[1]), "+f"(c[2]), "+f"(c[3])
    : "r"(a0), "r"(a1), "r"(a2), "r"(a3), "r"(b0), "r"(b1));
}

// ---- kernel 1: strided conv = gathered GEMM. 512 blocks, 128 t-rows each.
__global__ void __launch_bounds__(256)
compress_kernel(const float* __restrict__ pre, const float* __restrict__ ker,
                const float* __restrict__ bias, float* __restrict__ outc)
{
  extern __shared__ unsigned sh[];
  unsigned* As = sh;              // [128][PAD]
  unsigned* Kt = sh + 128*PAD;    // [64][PAD]  ker chunk transposed [dout][din]
  int tid = threadIdx.x, warp = tid>>5, lane = tid&31;
  int gid = lane>>2, tig = lane&3;
  int bh = blockIdx.x>>2, t0 = (blockIdx.x&3)*128;
  int b = bh>>4, h = bh&15;
  const float* base = pre + ((size_t)b*SS*HH + h)*DD;

  float acc[8][4];
  #pragma unroll
  for (int j=0;j<8;j++) acc[j][0]=acc[j][1]=acc[j][2]=acc[j][3]=0.f;

  for (int w=0; w<WW; w++){
    __syncthreads();
    #pragma unroll
    for (int i=0;i<8;i++){
      int idx = tid + i*256, r = idx>>4, c4 = idx&15;
      int s = (t0+r)*WW + w;
      float4 v = *reinterpret_cast<const float4*>(base + (size_t)s*HH*DD + c4*4);
      unsigned* d = As + r*PAD + c4*4;
      d[0]=f2tf(v.x); d[1]=f2tf(v.y); d[2]=f2tf(v.z); d[3]=f2tf(v.w);
    }
    #pragma unroll
    for (int i=0;i<4;i++){
      int idx = tid + i*256, din = idx>>4, d4 = idx&15;
      float4 v = *reinterpret_cast<const float4*>(ker + w*DD*DD + din*DD + d4*4);
      Kt[(d4*4+0)*PAD + din]=f2tf(v.x); Kt[(d4*4+1)*PAD + din]=f2tf(v.y);
      Kt[(d4*4+2)*PAD + din]=f2tf(v.z); Kt[(d4*4+3)*PAD + din]=f2tf(v.w);
    }
    __syncthreads();
    int m0 = warp*16;
    #pragma unroll
    for (int k8=0;k8<8;k8++){
      int k0 = k8*8;
      unsigned a0 = As[(m0+gid  )*PAD + k0+tig];
      unsigned a1 = As[(m0+gid+8)*PAD + k0+tig];
      unsigned a2 = As[(m0+gid  )*PAD + k0+tig+4];
      unsigned a3 = As[(m0+gid+8)*PAD + k0+tig+4];
      #pragma unroll
      for (int j=0;j<8;j++)
        mma8(acc[j], a0,a1,a2,a3, Kt[(j*8+gid)*PAD+k0+tig], Kt[(j*8+gid)*PAD+k0+tig+4]);
    }
  }
  int m0 = warp*16;
  #pragma unroll
  for (int j=0;j<8;j++){
    int col = j*8 + tig*2;
    float b0 = bias[col], b1 = bias[col+1];
    int rlo = t0+m0+gid, rhi = rlo+8;
    float2 vl, vh;
    vl.x=__uint_as_float(f2tf(acc[j][0]+b0)); vl.y=__uint_as_float(f2tf(acc[j][1]+b1));
    vh.x=__uint_as_float(f2tf(acc[j][2]+b0)); vh.y=__uint_as_float(f2tf(acc[j][3]+b1));
    *reinterpret_cast<float2*>(outc + ((size_t)bh*SC+rlo)*DD + col) = vl;
    *reinterpret_cast<float2*>(outc + ((size_t)bh*SC+rhi)*DD + col) = vh;
  }
}

// ---- kernel 2: flash attention. grid (16, 128): 128 queries per block.
__global__ void __launch_bounds__(256)
attn_kernel(const float* __restrict__ preq)
{
  extern __shared__ unsigned sh[];
  unsigned* Qs = sh;              // [128][PAD]
  unsigned* Ks = Qs + 128*PAD;    // [64][PAD]
  unsigned* VT = Ks + 64*PAD;     // [64][PAD]  V^T
  unsigned* Ps = VT + 64*PAD;     // [128][PAD]
  int tid = threadIdx.x, warp = tid>>5, lane = tid&31;
  int gid = lane>>2, tig = lane&3;
  int bh = blockIdx.y, b = bh>>4, h = bh&15;
  int q0 = blockIdx.x*128, m0 = warp*16;
  const float* qb = preq + ((size_t)b*SS*HH + h)*DD;
  const float* kb = g_kc + (size_t)bh*SC*DD;
  const float* vb = g_vc + (size_t)bh*SC*DD;

  #pragma unroll
  for (int i=0;i<8;i++){
    int idx = tid + i*256, r = idx>>4, c4 = idx&15;
    float4 v = *reinterpret_cast<const float4*>(qb + (size_t)(q0+r)*HH*DD + c4*4);
    unsigned* d = Qs + r*PAD + c4*4;
    d[0]=f2tf(v.x); d[1]=f2tf(v.y); d[2]=f2tf(v.z); d[3]=f2tf(v.w);
  }

  float o[8][4];
  #pragma unroll
  for (int j=0;j<8;j++) o[j][0]=o[j][1]=o[j][2]=o[j][3]=0.f;
  float m_lo=-1e30f, m_hi=-1e30f, l_lo=0.f, l_hi=0.f;
  const float scale = 0.125f;

  for (int ch=0; ch<8; ch++){
    __syncthreads();
    int c0 = ch*64;
    #pragma unroll
    for (int i=0;i<4;i++){
      int idx = tid + i*256, r = idx>>4, c4 = idx&15;
      float4 v = *reinterpret_cast<const float4*>(kb + (size_t)(c0+r)*DD + c4*4);
      unsigned* d = Ks + r*PAD + c4*4;
      d[0]=__float_as_uint(v.x); d[1]=__float_as_uint(v.y);
      d[2]=__float_as_uint(v.z); d[3]=__float_as_uint(v.w);
    }
    #pragma unroll
    for (int i=0;i<4;i++){
      int idx = tid + i*256, r = idx>>4, d4 = idx&15;
      float4 v = *reinterpret_cast<const float4*>(vb + (size_t)(c0+r)*DD + d4*4);
      VT[(d4*4+0)*PAD + r]=__float_as_uint(v.x); VT[(d4*4+1)*PAD + r]=__float_as_uint(v.y);
      VT[(d4*4+2)*PAD + r]=__float_as_uint(v.z); VT[(d4*4+3)*PAD + r]=__float_as_uint(v.w);
    }
    __syncthreads();

    float s[8][4];
    #pragma unroll
    for (int j=0;j<8;j++) s[j][0]=s[j][1]=s[j][2]=s[j][3]=0.f;
    #pragma unroll
    for (int k8=0;k8<8;k8++){
      int k0 = k8*8;
      unsigned a0 = Qs[(m0+gid  )*PAD + k0+tig];
      unsigned a1 = Qs[(m0+gid+8)*PAD + k0+tig];
      unsigned a2 = Qs[(m0+gid  )*PAD + k0+tig+4];
      unsigned a3 = Qs[(m0+gid+8)*PAD + k0+tig+4];
      #pragma unroll
      for (int j=0;j<8;j++)
        mma8(s[j], a0,a1,a2,a3, Ks[(j*8+gid)*PAD+k0+tig], Ks[(j*8+gid)*PAD+k0+tig+4]);
    }

    float mx_lo=-1e30f, mx_hi=-1e30f;
    #pragma unroll
    for (int j=0;j<8;j++){
      s[j][0]*=scale; s[j][1]*=scale; s[j][2]*=scale; s[j][3]*=scale;
      mx_lo = fmaxf(mx_lo, fmaxf(s[j][0], s[j][1]));
      mx_hi = fmaxf(mx_hi, fmaxf(s[j][2], s[j][3]));
    }
    mx_lo = fmaxf(mx_lo, __shfl_xor_sync(~0u, mx_lo, 1));
    mx_lo = fmaxf(mx_lo, __shfl_xor_sync(~0u, mx_lo, 2));
    mx_hi = fmaxf(mx_hi, __shfl_xor_sync(~0u, mx_hi, 1));
    mx_hi = fmaxf(mx_hi, __shfl_xor_sync(~0u, mx_hi, 2));
    float mn_lo = fmaxf(m_lo, mx_lo), mn_hi = fmaxf(m_hi, mx_hi);
    float al = __expf(m_lo-mn_lo), ah = __expf(m_hi-mn_hi);
    float rl = 0.f, rh = 0.f;
    #pragma unroll
    for (int j=0;j<8;j++){
      float p0=__expf(s[j][0]-mn_lo), p1=__expf(s[j][1]-mn_lo);
      float p2=__expf(s[j][2]-mn_hi), p3=__expf(s[j][3]-mn_hi);
      rl += p0+p1; rh += p2+p3;
      unsigned* plo = Ps + (m0+gid  )*PAD + j*8 + tig*2;
      unsigned* phi = Ps + (m0+gid+8)*PAD + j*8 + tig*2;
      plo[0]=f2tf(p0); plo[1]=f2tf(p1); phi[0]=f2tf(p2); phi[1]=f2tf(p3);
    }
    rl += __shfl_xor_sync(~0u, rl, 1); rl += __shfl_xor_sync(~0u, rl, 2);
    rh += __shfl_xor_sync(~0u, rh, 1); rh += __shfl_xor_sync(~0u, rh, 2);
    l_lo = l_lo*al + rl; l_hi = l_hi*ah + rh;
    m_lo = mn_lo; m_hi = mn_hi;
    #pragma unroll
    for (int j=0;j<8;j++){ o[j][0]*=al; o[j][1]*=al; o[j][2]*=ah; o[j][3]*=ah; }
    __syncwarp();

    #pragma unroll
    for (int k8=0;k8<8;k8++){
      int k0 = k8*8;
      unsigned a0 = Ps[(m0+gid  )*PAD + k0+tig];
      unsigned a1 = Ps[(m0+gid+8)*PAD + k0+tig];
      unsigned a2 = Ps[(m0+gid  )*PAD + k0+tig+4];
      unsigned a3 = Ps[(m0+gid+8)*PAD + k0+tig+4];
      #pragma unroll
      for (int j=0;j<8;j++)
        mma8(o[j], a0,a1,a2,a3, VT[(j*8+gid)*PAD+k0+tig], VT[(j*8+gid)*PAD+k0+tig+4]);
    }
  }

  float il = 1.f/l_lo, ih = 1.f/l_hi;
  int qlo = q0+m0+gid, qhi = qlo+8;
  float* olo = g_ao + ((size_t)(b*SS+qlo)*HH + h)*DD;
  float* ohi = g_ao + ((size_t)(b*SS+qhi)*HH + h)*DD;
  #pragma unroll
  for (int j=0;j<8;j++){
    int col = j*8 + tig*2;
    float2 vl, vh;
    vl.x=__uint_as_float(f2tf(o[j][0]*il)); vl.y=__uint_as_float(f2tf(o[j][1]*il));
    vh.x=__uint_as_float(f2tf(o[j][2]*ih)); vh.y=__uint_as_float(f2tf(o[j][3]*ih));
    *reinterpret_cast<float2*>(olo + col) = vl;
    *reinterpret_cast<float2*>(ohi + col) = vh;
  }
}

// ---- kernel 3: projection 16384x1024 @ 1024x1024. grid (128, 8).
__global__ void __launch_bounds__(256)
proj_kernel(const float* __restrict__ Wm, float* __restrict__ out)
{
  __shared__ unsigned As[128*PPAD];
  __shared__ unsigned Bs[128*PPAD];  // W^T chunk [n][k]
  int tid = threadIdx.x, warp = tid>>5, lane = tid&31;
  int gid = lane>>2, tig = lane&3;
  int r0 = blockIdx.x*128, n0 = blockIdx.y*128, m0 = warp*16;

  float acc[16][4];
  #pragma unroll
  for (int j=0;j<16;j++) acc[j][0]=acc[j][1]=acc[j][2]=acc[j][3]=0.f;

  for (int kc=0; kc<32; kc++){
    int k0g = kc*32;
    __syncthreads();
    #pragma unroll
    for (int i=0;i<4;i++){
      int idx = tid + i*256, r = idx>>3, c4 = idx&7;
      float4 v = *reinterpret_cast<const float4*>(g_ao + (size_t)(r0+r)*DM + k0g + c4*4);
      unsigned* d = As + r*PPAD + c4*4;
      d[0]=__float_as_uint(v.x); d[1]=__float_as_uint(v.y);
      d[2]=__float_as_uint(v.z); d[3]=__float_as_uint(v.w);
    }
    #pragma unroll
    for (int i=0;i<4;i++){
      int idx = tid + i*256, k = idx>>5, n4 = idx&31;
      float4 v = *reinterpret_cast<const float4*>(Wm + (size_t)(k0g+k)*DM + n0 + n4*4);
      Bs[(n4*4+0)*PPAD + k]=f2tf(v.x); Bs[(n4*4+1)*PPAD + k]=f2tf(v.y);
      Bs[(n4*4+2)*PPAD + k]=f2tf(v.z); Bs[(n4*4+3)*PPAD + k]=f2tf(v.w);
    }
    __syncthreads();
    #pragma unroll
    for (int k8=0;k8<4;k8++){
      int k0 = k8*8;
      unsigned a0 = As[(m0+gid  )*PPAD + k0+tig];
      unsigned a1 = As[(m0+gid+8)*PPAD + k0+tig];
      unsigned a2 = As[(m0+gid  )*PPAD + k0+tig+4];
      unsigned a3 = As[(m0+gid+8)*PPAD + k0+tig+4];
      #pragma unroll
      for (int j=0;j<16;j++)
        mma8(acc[j], a0,a1,a2,a3, Bs[(j*8+gid)*PPAD+k0+tig], Bs[(j*8+gid)*PPAD+k0+tig+4]);
    }
  }
  #pragma unroll
  for (int j=0;j<16;j++){
    int col = n0 + j*8 + tig*2;
    int rlo = r0+m0+gid, rhi = rlo+8;
    *reinterpret_cast<float2*>(out + (size_t)rlo*DM + col) = make_float2(acc[j][0], acc[j][1]);
    *reinterpret_cast<float2*>(out + (size_t)rhi*DM + col) = make_float2(acc[j][2], acc[j][3]);
  }
}

extern "C" void kernel_launch(void* const* d_in, const int* in_sizes, int n_in,
                              void* d_out, int out_size)
{
  const float* pre_q = (const float*)d_in[0];
  const float* pre_k = (const float*)d_in[1];
  const float* pre_v = (const float*)d_in[2];
  const float* kker  = (const float*)d_in[3];
  const float* kbias = (const float*)d_in[4];
  const float* vker  = (const float*)d_in[5];
  const float* vbias = (const float*)d_in[6];
  const float* ow    = (const float*)d_in[7];
  float* out = (float*)d_out;

  float *g_kc_p, *g_vc_p;
  cudaGetSymbolAddress((void**)&g_kc_p, g_kc);
  cudaGetSymbolAddress((void**)&g_vc_p, g_vc);

  const int smem1 = 192*PAD*4;   // 52224
  const int smem2 = 384*PAD*4;   // 104448
  cudaFuncSetAttribute(compress_kernel, cudaFuncAttributeMaxDynamicSharedMemorySize, smem1);
  cudaFuncSetAttribute(attn_kernel, cudaFuncAttributeMaxDynamicSharedMemorySize, smem2);

  compress_kernel<<<512, 256, smem1>>>(pre_k, kker, kbias, g_kc_p);
  compress_kernel<<<512, 256, smem1>>>(pre_v, vker, vbias, g_vc_p);
  attn_kernel<<<dim3(16,128), 256, smem2>>>(pre_q);
  proj_kernel<<<dim3(128,8), 256>>>(ow, out);
}

// round 3
// speedup vs baseline: 1.1174x; 1.1174x over previous
#include <cuda_runtime.h>
#include <cstdint>

#define BB 8
#define SS 2048
#define HH 16
#define DD 64
#define DM 1024
#define SC 512

__device__ float g_kc[BB*HH*SC*DD];
__device__ float g_vc[BB*HH*SC*DD];
__device__ float g_ao[BB*SS*DM];

__device__ __forceinline__ unsigned f2tf(float x){
  unsigned u; asm("cvt.rna.tf32.f32 %0, %1;" : "=r"(u) : "f"(x)); return u;
}
__device__ __forceinline__ void mma8(float* c, uint4 a, unsigned b0, unsigned b1){
  asm volatile(
    "mma.sync.aligned.m16n8k8.row.col.f32.tf32.tf32.f32 "
    "{%0,%1,%2,%3},{%4,%5,%6,%7},{%8,%9},{%0,%1,%2,%3};"
    : "+f"(c[0]), "+f"(c[1]), "+f"(c[2]), "+f"(c[3])
    : "r"(a.x), "r"(a.y), "r"(a.z), "r"(a.w), "r"(b0), "r"(b1));
}

// ============ kernel 1: strided conv (gathered GEMM 128x64, K=256) ========
// grid 512. 8 warps as 4m x 2n; warp tile 32m x 32n. Double-buffered over w.
__global__ void __launch_bounds__(256,2)
compress_kernel(const float* __restrict__ pre, const float* __restrict__ ker,
                const float* __restrict__ bias, float* __restrict__ outc)
{
  extern __shared__ unsigned sh[];
  unsigned* Af = sh;            // 2 x 8192 words  (tiles: mt8 x k8_8)
  unsigned* Bf = sh + 16384;    // 2 x 4096 words  (tiles: nt8 x kp4)
  int tid=threadIdx.x, warp=tid>>5, lane=tid&31, gid=lane>>2, tig=lane&3;
  int bh = blockIdx.x>>2, t0 = (blockIdx.x&3)*128;
  int b = bh>>4, h = bh&15;
  const float* base = pre + ((size_t)b*SS*HH + h)*DD;
  int wm = warp>>1, wn = warp&1;

  float acc[2][4][4];
  #pragma unroll
  for (int m=0;m<2;m++)
    #pragma unroll
    for (int j=0;j<4;j++) acc[m][j][0]=acc[m][j][1]=acc[m][j][2]=acc[m][j][3]=0.f;

  auto stage = [&](int w, int bf){
    #pragma unroll
    for (int i=0;i<8;i++){                 // A tiles: id = mt*8 + k8
      int id = warp*8+i, mt = id>>3, k8 = id&7;
      const float* g = base + (size_t)((t0+mt*16+gid)*4 + w)*(HH*DD) + k8*8+tig;
      uint4 u;
      u.x=f2tf(g[0]); u.y=f2tf(g[8*4*HH*DD]); u.z=f2tf(g[4]); u.w=f2tf(g[8*4*HH*DD+4]);
      *reinterpret_cast<uint4*>(&Af[bf*8192 + id*128 + lane*4]) = u;
    }
    #pragma unroll
    for (int i=0;i<4;i++){                 // B tiles: id = nt*4 + kp
      int id = warp*4+i, nt = id>>2, kp = id&3;
      const float* g = ker + w*DD*DD + (kp*16+tig)*DD + nt*8+gid;
      uint4 u;
      u.x=f2tf(g[0]); u.y=f2tf(g[4*DD]); u.z=f2tf(g[8*DD]); u.w=f2tf(g[12*DD]);
      *reinterpret_cast<uint4*>(&Bf[bf*4096 + id*128 + lane*4]) = u;
    }
  };

  stage(0,0); __syncthreads();
  for (int w=0; w<4; w++){
    int bf = w&1;
    if (w<3) stage(w+1, bf^1);
    #pragma unroll
    for (int kp=0;kp<4;kp++){
      uint4 bb[4];
      #pragma unroll
      for (int j=0;j<4;j++)
        bb[j] = *reinterpret_cast<const uint4*>(&Bf[bf*4096 + ((wn*4+j)*4+kp)*128 + lane*4]);
      #pragma unroll
      for (int m=0;m<2;m++){
        uint4 a0 = *reinterpret_cast<const uint4*>(&Af[bf*8192 + ((wm*2+m)*8 + kp*2  )*128 + lane*4]);
        uint4 a1 = *reinterpret_cast<const uint4*>(&Af[bf*8192 + ((wm*2+m)*8 + kp*2+1)*128 + lane*4]);
        #pragma unroll
        for (int j=0;j<4;j++){
          mma8(acc[m][j], a0, bb[j].x, bb[j].y);
          mma8(acc[m][j], a1, bb[j].z, bb[j].w);
        }
      }
    }
    __syncthreads();
  }

  #pragma unroll
  for (int m=0;m<2;m++){
    int rlo = t0 + wm*32 + m*16 + gid, rhi = rlo+8;
    #pragma unroll
    for (int j=0;j<4;j++){
      int col = wn*32 + j*8 + tig*2;
      float b0 = bias[col], b1 = bias[col+1];
      float2 vl, vh;
      vl.x=__uint_as_float(f2tf(acc[m][j][0]+b0)); vl.y=__uint_as_float(f2tf(acc[m][j][1]+b1));
      vh.x=__uint_as_float(f2tf(acc[m][j][2]+b0)); vh.y=__uint_as_float(f2tf(acc[m][j][3]+b1));
      *reinterpret_cast<float2*>(outc + ((size_t)bh*SC+rlo)*DD + col) = vl;
      *reinterpret_cast<float2*>(outc + ((size_t)bh*SC+rhi)*DD + col) = vh;
    }
  }
}

// ============ kernel 2: flash attention, Q in registers ====================
// grid (16,128). 8 warps x 16q. K/V double-buffered fragment-layout smem.
__global__ void __launch_bounds__(256,2)
attn_kernel(const float* __restrict__ preq)
{
  extern __shared__ unsigned sh[];
  unsigned* Kf = sh;            // 2 x 4096  (tiles nt8 x kp4)
  unsigned* Vf = sh + 8192;     // 2 x 4096
  unsigned* Pf = sh + 16384;    // 8 warps x 1024 (A-frag: k8_8 x lane x 4)
  int tid=threadIdx.x, warp=tid>>5, lane=tid&31, gid=lane>>2, tig=lane&3;
  int bh = blockIdx.y, b = bh>>4, h = bh&15;
  int q0 = blockIdx.x*128, m0 = warp*16;
  const float* qb = preq + ((size_t)b*SS*HH + h)*DD;
  const float* kb = g_kc + (size_t)bh*SC*DD;
  const float* vb = g_vc + (size_t)bh*SC*DD;

  // Q fragments -> registers (gathered; persists all 8 chunks)
  uint4 q[8];
  {
    const float* qr = qb + (size_t)(q0+m0+gid)*(HH*DD) + tig;
    #pragma unroll
    for (int k8=0;k8<8;k8++){
      q[k8].x = f2tf(qr[k8*8]);
      q[k8].y = f2tf(qr[8*HH*DD + k8*8]);
      q[k8].z = f2tf(qr[k8*8+4]);
      q[k8].w = f2tf(qr[8*HH*DD + k8*8+4]);
    }
  }

  float o[8][4];
  #pragma unroll
  for (int j=0;j<8;j++) o[j][0]=o[j][1]=o[j][2]=o[j][3]=0.f;
  float m_lo=-1e30f, m_hi=-1e30f, l_lo=0.f, l_hi=0.f;
  const float scale = 0.125f;

  auto stage = [&](int ch, int bf){
    int c0 = ch*64;
    #pragma unroll
    for (int i=0;i<4;i++){
      int id = warp*4+i, nt = id>>2, kp = id&3;
      const float* g = kb + (size_t)(c0+nt*8+gid)*DD + kp*16+tig;
      uint4 u;
      u.x=__float_as_uint(g[0]); u.y=__float_as_uint(g[4]);
      u.z=__float_as_uint(g[8]); u.w=__float_as_uint(g[12]);
      *reinterpret_cast<uint4*>(&Kf[bf*4096 + id*128 + lane*4]) = u;
      const float* gv = vb + (size_t)(c0+kp*16+tig)*DD + nt*8+gid;
      uint4 v;
      v.x=__float_as_uint(gv[0]); v.y=__float_as_uint(gv[4*DD]);
      v.z=__float_as_uint(gv[8*DD]); v.w=__float_as_uint(gv[12*DD]);
      *reinterpret_cast<uint4*>(&Vf[bf*4096 + id*128 + lane*4]) = v;
    }
  };

  stage(0,0); __syncthreads();

  for (int ch=0; ch<8; ch++){
    int bf = ch&1;
    if (ch<7) stage(ch+1, bf^1);

    float s[8][4];
    #pragma unroll
    for (int j=0;j<8;j++) s[j][0]=s[j][1]=s[j][2]=s[j][3]=0.f;
    #pragma unroll
    for (int kp=0;kp<4;kp++){
      #pragma unroll
      for (int j=0;j<8;j++){
        uint4 bb = *reinterpret_cast<const uint4*>(&Kf[bf*4096 + (j*4+kp)*128 + lane*4]);
        mma8(s[j], q[kp*2],   bb.x, bb.y);
        mma8(s[j], q[kp*2+1], bb.z, bb.w);
      }
    }

    float mx_lo=-1e30f, mx_hi=-1e30f;
    #pragma unroll
    for (int j=0;j<8;j++){
      s[j][0]*=scale; s[j][1]*=scale; s[j][2]*=scale; s[j][3]*=scale;
      mx_lo = fmaxf(mx_lo, fmaxf(s[j][0], s[j][1]));
      mx_hi = fmaxf(mx_hi, fmaxf(s[j][2], s[j][3]));
    }
    mx_lo = fmaxf(mx_lo, __shfl_xor_sync(~0u, mx_lo, 1));
    mx_lo = fmaxf(mx_lo, __shfl_xor_sync(~0u, mx_lo, 2));
    mx_hi = fmaxf(mx_hi, __shfl_xor_sync(~0u, mx_hi, 1));
    mx_hi = fmaxf(mx_hi, __shfl_xor_sync(~0u, mx_hi, 2));
    float mn_lo = fmaxf(m_lo, mx_lo), mn_hi = fmaxf(m_hi, mx_hi);
    float al = __expf(m_lo-mn_lo), ah = __expf(m_hi-mn_hi);
    float rl = 0.f, rh = 0.f;
    // P -> A-fragment layout in Pf (warp-private region)
    int t0p = (tig*2)&3, t1p = (tig*2+1)&3, kk = tig>>1;
    #pragma unroll
    for (int j=0;j<8;j++){
      float p0=__expf(s[j][0]-mn_lo), p1=__expf(s[j][1]-mn_lo);
      float p2=__expf(s[j][2]-mn_hi), p3=__expf(s[j][3]-mn_hi);
      rl += p0+p1; rh += p2+p3;
      unsigned bj = warp*1024 + j*128;
      Pf[bj + (gid*4+t0p)*4 + 2*kk    ] = f2tf(p0);
      Pf[bj + (gid*4+t1p)*4 + 2*kk    ] = f2tf(p1);
      Pf[bj + (gid*4+t0p)*4 + 2*kk + 1] = f2tf(p2);
      Pf[bj + (gid*4+t1p)*4 + 2*kk + 1] = f2tf(p3);
    }
    rl += __shfl_xor_sync(~0u, rl, 1); rl += __shfl_xor_sync(~0u, rl, 2);
    rh += __shfl_xor_sync(~0u, rh, 1); rh += __shfl_xor_sync(~0u, rh, 2);
    l_lo = l_lo*al + rl; l_hi = l_hi*ah + rh;
    m_lo = mn_lo; m_hi = mn_hi;
    #pragma unroll
    for (int j=0;j<8;j++){ o[j][0]*=al; o[j][1]*=al; o[j][2]*=ah; o[j][3]*=ah; }
    __syncwarp();

    #pragma unroll
    for (int kp=0;kp<4;kp++){
      uint4 a0 = *reinterpret_cast<const uint4*>(&Pf[warp*1024 + (kp*2  )*128 + lane*4]);
      uint4 a1 = *reinterpret_cast<const uint4*>(&Pf[warp*1024 + (kp*2+1)*128 + lane*4]);
      #pragma unroll
      for (int j=0;j<8;j++){
        uint4 vv = *reinterpret_cast<const uint4*>(&Vf[bf*4096 + (j*4+kp)*128 + lane*4]);
        mma8(o[j], a0, vv.x, vv.y);
        mma8(o[j], a1, vv.z, vv.w);
      }
    }
    __syncthreads();
  }

  float il = 1.f/l_lo, ih = 1.f/l_hi;
  int qlo = q0+m0+gid, qhi = qlo+8;
  float* olo = g_ao + ((size_t)(b*SS+qlo)*HH + h)*DD;
  float* ohi = g_ao + ((size_t)(b*SS+qhi)*HH + h)*DD;
  #pragma unroll
  for (int j=0;j<8;j++){
    int col = j*8 + tig*2;
    float2 vl, vh;
    vl.x=__uint_as_float(f2tf(o[j][0]*il)); vl.y=__uint_as_float(f2tf(o[j][1]*il));
    vh.x=__uint_as_float(f2tf(o[j][2]*ih)); vh.y=__uint_as_float(f2tf(o[j][3]*ih));
    *reinterpret_cast<float2*>(olo + col) = vl;
    *reinterpret_cast<float2*>(ohi + col) = vh;
  }
}

// ============ kernel 3: projection 16384x1024 @ 1024x1024 ==================
// grid (128,8). 8 warps as 4m x 2n; warp 32m x 64n. k-chunk 32, double-buffered.
__global__ void __launch_bounds__(256,2)
proj_kernel(const float* __restrict__ Wm, float* __restrict__ out)
{
  extern __shared__ unsigned sh[];
  unsigned* Af = sh;            // 2 x 4096 (tiles mt8 x k8_4)
  unsigned* Bf = sh + 8192;     // 2 x 4096 (tiles nt16 x kp2)
  int tid=threadIdx.x, warp=tid>>5, lane=tid&31, gid=lane>>2, tig=lane&3;
  int r0 = blockIdx.x*128, n0 = blockIdx.y*128;
  int wm = warp>>1, wn = warp&1;

  float acc[2][8][4];
  #pragma unroll
  for (int m=0;m<2;m++)
    #pragma unroll
    for (int j=0;j<8;j++) acc[m][j][0]=acc[m][j][1]=acc[m][j][2]=acc[m][j][3]=0.f;

  auto stage = [&](int kc, int bf){
    #pragma unroll
    for (int i=0;i<4;i++){                 // A tiles: id = mt*4 + k8
      int id = warp*4+i, mt = id>>2, k8 = id&3;
      const float* g = g_ao + (size_t)(r0+mt*16+gid)*DM + kc*32 + k8*8 + tig;
      uint4 u;
      u.x=__float_as_uint(g[0]); u.y=__float_as_uint(g[8*DM]);
      u.z=__float_as_uint(g[4]); u.w=__float_as_uint(g[8*DM+4]);
      *reinterpret_cast<uint4*>(&Af[bf*4096 + id*128 + lane*4]) = u;
    }
    #pragma unroll
    for (int i=0;i<4;i++){                 // B tiles: id = nt*2 + kp
      int id = warp*4+i, nt = id>>1, kp = id&1;
      const float* g = Wm + (size_t)(kc*32 + kp*16 + tig)*DM + n0 + nt*8 + gid;
      uint4 u;
      u.x=f2tf(g[0]); u.y=f2tf(g[4*DM]); u.z=f2tf(g[8*DM]); u.w=f2tf(g[12*DM]);
      *reinterpret_cast<uint4*>(&Bf[bf*4096 + id*128 + lane*4]) = u;
    }
  };

  stage(0,0); __syncthreads();
  for (int kc=0; kc<32; kc++){
    int bf = kc&1;
    if (kc<31) stage(kc+1, bf^1);
    #pragma unroll
    for (int kp=0;kp<2;kp++){
      uint4 bb[8];
      #pragma unroll
      for (int j=0;j<8;j++)
        bb[j] = *reinterpret_cast<const uint4*>(&Bf[bf*4096 + (((wn*8+j)*2)+kp)*128 + lane*4]);
      #pragma unroll
      for (int m=0;m<2;m++){
        uint4 a0 = *reinterpret_cast<const uint4*>(&Af[bf*4096 + ((wm*2+m)*4 + kp*2  )*128 + lane*4]);
        uint4 a1 = *reinterpret_cast<const uint4*>(&Af[bf*4096 + ((wm*2+m)*4 + kp*2+1)*128 + lane*4]);
        #pragma unroll
        for (int j=0;j<8;j++){
          mma8(acc[m][j], a0, bb[j].x, bb[j].y);
          mma8(acc[m][j], a1, bb[j].z, bb[j].w);
        }
      }
    }
    __syncthreads();
  }

  #pragma unroll
  for (int m=0;m<2;m++){
    int rlo = r0 + wm*32 + m*16 + gid, rhi = rlo+8;
    #pragma unroll
    for (int j=0;j<8;j++){
      int col = n0 + wn*64 + j*8 + tig*2;
      *reinterpret_cast<float2*>(out + (size_t)rlo*DM + col) = make_float2(acc[m][j][0], acc[m][j][1]);
      *reinterpret_cast<float2*>(out + (size_t)rhi*DM + col) = make_float2(acc[m][j][2], acc[m][j][3]);
    }
  }
}

extern "C" void kernel_launch(void* const* d_in, const int* in_sizes, int n_in,
                              void* d_out, int out_size)
{
  const float* pre_q = (const float*)d_in[0];
  const float* pre_k = (const float*)d_in[1];
  const float* pre_v = (const float*)d_in[2];
  const float* kker  = (const float*)d_in[3];
  const float* kbias = (const float*)d_in[4];
  const float* vker  = (const float*)d_in[5];
  const float* vbias = (const float*)d_in[6];
  const float* ow    = (const float*)d_in[7];
  float* out = (float*)d_out;

  float *g_kc_p, *g_vc_p;
  cudaGetSymbolAddress((void**)&g_kc_p, g_kc);
  cudaGetSymbolAddress((void**)&g_vc_p, g_vc);

  const int smemC = 24576*4;   // 98304
  const int smemA = 24576*4;   // 98304
  const int smemP = 16384*4;   // 65536
  cudaFuncSetAttribute(compress_kernel, cudaFuncAttributeMaxDynamicSharedMemorySize, smemC);
  cudaFuncSetAttribute(attn_kernel, cudaFuncAttributeMaxDynamicSharedMemorySize, smemA);
  cudaFuncSetAttribute(proj_kernel, cudaFuncAttributeMaxDynamicSharedMemorySize, smemP);

  compress_kernel<<<512, 256, smemC>>>(pre_k, kker, kbias, g_kc_p);
  compress_kernel<<<512, 256, smemC>>>(pre_v, vker, vbias, g_vc_p);
  attn_kernel<<<dim3(16,128), 256, smemA>>>(pre_q);
  proj_kernel<<<dim3(128,8), 256, smemP>>>(ow, out);
}

// round 4
// speedup vs baseline: 1.4825x; 1.3267x over previous
#include <cuda_runtime.h>
#include <cstdint>

#define BB 8
#define SS 2048
#define HH 16
#define DD 64
#define DM 1024
#define SC 512

__device__ float g_kc[BB*HH*SC*DD];        // [bh][c][d]
__device__ float g_vc[BB*HH*DD*SC];        // [bh][d][c]  (transposed)
__device__ float g_ao[BB*SS*DM];           // attention out (tf32-rounded bits)
__device__ float g_wt[DM*DM];              // W^T: [n][k]

__device__ __forceinline__ unsigned f2tf(float x){
  unsigned u; asm("cvt.rna.tf32.f32 %0, %1;" : "=r"(u) : "f"(x)); return u;
}
__device__ __forceinline__ void mma8(float* c, uint4 a, unsigned b0, unsigned b1){
  asm volatile(
    "mma.sync.aligned.m16n8k8.row.col.f32.tf32.tf32.f32 "
    "{%0,%1,%2,%3},{%4,%5,%6,%7},{%8,%9},{%0,%1,%2,%3};"
    : "+f"(c[0]), "+f"(c[1]), "+f"(c[2]), "+f"(c[3])
    : "r"(a.x), "r"(a.y), "r"(a.z), "r"(a.w), "r"(b0), "r"(b1));
}
__device__ __forceinline__ uint4 ldsm4(unsigned addr){
  uint4 r;
  asm volatile("ldmatrix.sync.aligned.m8n8.x4.shared.b16 {%0,%1,%2,%3}, [%4];"
    : "=r"(r.x), "=r"(r.y), "=r"(r.z), "=r"(r.w) : "r"(addr));
  return r;
}

// ============ kernel 0: W -> W^T ==========================================
__global__ void __launch_bounds__(256)
transpose_w(const float* __restrict__ W, float* __restrict__ Wt)
{
  __shared__ float t[32][33];
  int bx = blockIdx.x*32, by = blockIdx.y*32;
  int tx = threadIdx.x & 31, ty = threadIdx.x >> 5;   // 32 x 8
  #pragma unroll
  for (int j=0;j<4;j++)
    t[ty+j*8][tx] = W[(size_t)(by+ty+j*8)*DM + bx+tx];
  __syncthreads();
  #pragma unroll
  for (int j=0;j<4;j++)
    Wt[(size_t)(bx+ty+j*8)*DM + by+tx] = t[tx][ty+j*8];
}

// ============ kernel 1: strided conv (gathered GEMM 128x64, K=256) ========
// grid 512. 8 warps as 4m x 2n; warp 32m x 32n. (unchanged from R3 + V-transpose)
__global__ void __launch_bounds__(256,2)
compress_kernel(const float* __restrict__ pre, const float* __restrict__ ker,
                const float* __restrict__ bias, float* __restrict__ outc,
                int transposed)
{
  extern __shared__ unsigned sh[];
  unsigned* Af = sh;
  unsigned* Bf = sh + 16384;
  int tid=threadIdx.x, warp=tid>>5, lane=tid&31, gid=lane>>2, tig=lane&3;
  int bh = blockIdx.x>>2, t0 = (blockIdx.x&3)*128;
  int b = bh>>4, h = bh&15;
  const float* base = pre + ((size_t)b*SS*HH + h)*DD;
  int wm = warp>>1, wn = warp&1;

  float acc[2][4][4];
  #pragma unroll
  for (int m=0;m<2;m++)
    #pragma unroll
    for (int j=0;j<4;j++) acc[m][j][0]=acc[m][j][1]=acc[m][j][2]=acc[m][j][3]=0.f;

  auto stage = [&](int w, int bf){
    #pragma unroll
    for (int i=0;i<8;i++){
      int id = warp*8+i, mt = id>>3, k8 = id&7;
      const float* g = base + (size_t)((t0+mt*16+gid)*4 + w)*(HH*DD) + k8*8+tig;
      uint4 u;
      u.x=f2tf(g[0]); u.y=f2tf(g[8*4*HH*DD]); u.z=f2tf(g[4]); u.w=f2tf(g[8*4*HH*DD+4]);
      *reinterpret_cast<uint4*>(&Af[bf*8192 + id*128 + lane*4]) = u;
    }
    #pragma unroll
    for (int i=0;i<4;i++){
      int id = warp*4+i, nt = id>>2, kp = id&3;
      const float* g = ker + w*DD*DD + (kp*16+tig)*DD + nt*8+gid;
      uint4 u;
      u.x=f2tf(g[0]); u.y=f2tf(g[4*DD]); u.z=f2tf(g[8*DD]); u.w=f2tf(g[12*DD]);
      *reinterpret_cast<uint4*>(&Bf[bf*4096 + id*128 + lane*4]) = u;
    }
  };

  stage(0,0); __syncthreads();
  for (int w=0; w<4; w++){
    int bf = w&1;
    if (w<3) stage(w+1, bf^1);
    #pragma unroll
    for (int kp=0;kp<4;kp++){
      uint4 bb[4];
      #pragma unroll
      for (int j=0;j<4;j++)
        bb[j] = *reinterpret_cast<const uint4*>(&Bf[bf*4096 + ((wn*4+j)*4+kp)*128 + lane*4]);
      #pragma unroll
      for (int m=0;m<2;m++){
        uint4 a0 = *reinterpret_cast<const uint4*>(&Af[bf*8192 + ((wm*2+m)*8 + kp*2  )*128 + lane*4]);
        uint4 a1 = *reinterpret_cast<const uint4*>(&Af[bf*8192 + ((wm*2+m)*8 + kp*2+1)*128 + lane*4]);
        #pragma unroll
        for (int j=0;j<4;j++){
          mma8(acc[m][j], a0, bb[j].x, bb[j].y);
          mma8(acc[m][j], a1, bb[j].z, bb[j].w);
        }
      }
    }
    __syncthreads();
  }

  #pragma unroll
  for (int m=0;m<2;m++){
    int rlo = t0 + wm*32 + m*16 + gid, rhi = rlo+8;
    #pragma unroll
    for (int j=0;j<4;j++){
      int col = wn*32 + j*8 + tig*2;
      float b0 = bias[col], b1 = bias[col+1];
      float v00=__uint_as_float(f2tf(acc[m][j][0]+b0));
      float v01=__uint_as_float(f2tf(acc[m][j][1]+b1));
      float v10=__uint_as_float(f2tf(acc[m][j][2]+b0));
      float v11=__uint_as_float(f2tf(acc[m][j][3]+b1));
      if (!transposed){
        *reinterpret_cast<float2*>(outc + ((size_t)bh*SC+rlo)*DD + col) = make_float2(v00,v01);
        *reinterpret_cast<float2*>(outc + ((size_t)bh*SC+rhi)*DD + col) = make_float2(v10,v11);
      } else {
        float* o0 = outc + ((size_t)bh*DD + col)*SC;
        float* o1 = outc + ((size_t)bh*DD + col+1)*SC;
        o0[rlo]=v00; o1[rlo]=v01; o0[rhi]=v10; o1[rhi]=v11;
      }
    }
  }
}

// ============ kernel 2: flash attention, ldmatrix K/V ======================
// grid (16,128). 8 warps x 16q. K/V row-major swizzled, double-buffered.
__global__ void __launch_bounds__(256,2)
attn_kernel(const float* __restrict__ preq)
{
  extern __shared__ unsigned sh[];
  // bytes: K tiles [2][64 rows][64 w] at 0, V at 32768, Pf at 65536
  unsigned sbase = (unsigned)__cvta_generic_to_shared(sh);
  unsigned* Pf = sh + 16384;    // 8 warps x 1024 words (A-frag layout)

  int tid=threadIdx.x, warp=tid>>5, lane=tid&31, gid=lane>>2, tig=lane&3;
  int mi = lane>>3, lrow = lane&7;
  int bh = blockIdx.y, b = bh>>4, h = bh&15;
  int q0 = blockIdx.x*128, m0 = warp*16;
  const float* qb = preq + ((size_t)b*SS*HH + h)*DD;
  const float* kb = g_kc + (size_t)bh*SC*DD;
  const float* vb = g_vc + (size_t)bh*DD*SC;

  // Q fragments -> registers
  uint4 q[8];
  {
    const float* qr = qb + (size_t)(q0+m0+gid)*(HH*DD) + tig;
    #pragma unroll
    for (int k8=0;k8<8;k8++){
      q[k8].x = f2tf(qr[k8*8]);
      q[k8].y = f2tf(qr[8*HH*DD + k8*8]);
      q[k8].z = f2tf(qr[k8*8+4]);
      q[k8].w = f2tf(qr[8*HH*DD + k8*8+4]);
    }
  }

  // per-lane ldmatrix B row geometry: row(jp) = jp*16 + (mi>>1)*8 + lrow
  int browb = (mi>>1)*8 + lrow;
  int bsel = mi&1;

  float o[8][4];
  #pragma unroll
  for (int j=0;j<8;j++) o[j][0]=o[j][1]=o[j][2]=o[j][3]=0.f;
  float m_lo=-1e30f, m_hi=-1e30f, l_lo=0.f, l_hi=0.f;
  const float scale = 0.125f;

  auto stage = [&](int ch, int bf){
    int c0 = ch*64;
    #pragma unroll
    for (int i=0;i<4;i++){
      int idx = tid + i*256, row = idx>>4, cv = idx&15;
      uint4 kv = *reinterpret_cast<const uint4*>(kb + (size_t)(c0+row)*DD + cv*4);
      *reinterpret_cast<uint4*>(&sh[bf*4096 + row*64 + ((cv ^ (row&7))*4)]) = kv;
      uint4 vv = *reinterpret_cast<const uint4*>(vb + (size_t)row*SC + c0 + cv*4);
      *reinterpret_cast<uint4*>(&sh[8192 + bf*4096 + row*64 + ((cv ^ (row&7))*4)]) = vv;
    }
  };

  stage(0,0); __syncthreads();

  for (int ch=0; ch<8; ch++){
    int bf = ch&1;
    if (ch<7) stage(ch+1, bf^1);
    unsigned Kb = sbase + bf*16384;
    unsigned Vb = sbase + 32768 + bf*16384;

    // S = Q K^T : B-frags via ldmatrix from K tile (rows=c, k=d)
    float s[8][4];
    #pragma unroll
    for (int j=0;j<8;j++) s[j][0]=s[j][1]=s[j][2]=s[j][3]=0.f;
    #pragma unroll
    for (int k8=0;k8<8;k8++){
      #pragma unroll
      for (int jp=0;jp<4;jp++){
        int row = jp*16 + browb;
        uint4 bb = ldsm4(Kb + row*256 + (((2*k8+bsel) ^ (row&7))<<4));
        mma8(s[2*jp],   q[k8], bb.x, bb.y);
        mma8(s[2*jp+1], q[k8], bb.z, bb.w);
      }
    }

    float mx_lo=-1e30f, mx_hi=-1e30f;
    #pragma unroll
    for (int j=0;j<8;j++){
      s[j][0]*=scale; s[j][1]*=scale; s[j][2]*=scale; s[j][3]*=scale;
      mx_lo = fmaxf(mx_lo, fmaxf(s[j][0], s[j][1]));
      mx_hi = fmaxf(mx_hi, fmaxf(s[j][2], s[j][3]));
    }
    mx_lo = fmaxf(mx_lo, __shfl_xor_sync(~0u, mx_lo, 1));
    mx_lo = fmaxf(mx_lo, __shfl_xor_sync(~0u, mx_lo, 2));
    mx_hi = fmaxf(mx_hi, __shfl_xor_sync(~0u, mx_hi, 1));
    mx_hi = fmaxf(mx_hi, __shfl_xor_sync(~0u, mx_hi, 2));
    float mn_lo = fmaxf(m_lo, mx_lo), mn_hi = fmaxf(m_hi, mx_hi);
    float al = __expf(m_lo-mn_lo), ah = __expf(m_hi-mn_hi);
    float rl = 0.f, rh = 0.f;
    int t0p = (tig*2)&3, t1p = (tig*2+1)&3, kk = tig>>1;
    #pragma unroll
    for (int j=0;j<8;j++){
      float p0=__expf(s[j][0]-mn_lo), p1=__expf(s[j][1]-mn_lo);
      float p2=__expf(s[j][2]-mn_hi), p3=__expf(s[j][3]-mn_hi);
      rl += p0+p1; rh += p2+p3;
      unsigned bj = warp*1024 + j*128;
      Pf[bj + (gid*4+t0p)*4 + 2*kk    ] = f2tf(p0);
      Pf[bj + (gid*4+t1p)*4 + 2*kk    ] = f2tf(p1);
      Pf[bj + (gid*4+t0p)*4 + 2*kk + 1] = f2tf(p2);
      Pf[bj + (gid*4+t1p)*4 + 2*kk + 1] = f2tf(p3);
    }
    rl += __shfl_xor_sync(~0u, rl, 1); rl += __shfl_xor_sync(~0u, rl, 2);
    rh += __shfl_xor_sync(~0u, rh, 1); rh += __shfl_xor_sync(~0u, rh, 2);
    l_lo = l_lo*al + rl; l_hi = l_hi*ah + rh;
    m_lo = mn_lo; m_hi = mn_hi;
    #pragma unroll
    for (int j=0;j<8;j++){ o[j][0]*=al; o[j][1]*=al; o[j][2]*=ah; o[j][3]*=ah; }
    __syncwarp();

    // O += P V : A = Pf frags (LDS.128), B = V tile (rows=d, k=c)
    #pragma unroll
    for (int k8=0;k8<8;k8++){
      uint4 a = *reinterpret_cast<const uint4*>(&Pf[warp*1024 + k8*128 + lane*4]);
      #pragma unroll
      for (int jp=0;jp<4;jp++){
        int row = jp*16 + browb;
        uint4 vv = ldsm4(Vb + row*256 + (((2*k8+bsel) ^ (row&7))<<4));
        mma8(o[2*jp],   a, vv.x, vv.y);
        mma8(o[2*jp+1], a, vv.z, vv.w);
      }
    }
    __syncthreads();
  }

  float il = 1.f/l_lo, ih = 1.f/l_hi;
  int qlo = q0+m0+gid, qhi = qlo+8;
  float* olo = g_ao + ((size_t)(b*SS+qlo)*HH + h)*DD;
  float* ohi = g_ao + ((size_t)(b*SS+qhi)*HH + h)*DD;
  #pragma unroll
  for (int j=0;j<8;j++){
    int col = j*8 + tig*2;
    float2 vl, vh;
    vl.x=__uint_as_float(f2tf(o[j][0]*il)); vl.y=__uint_as_float(f2tf(o[j][1]*il));
    vh.x=__uint_as_float(f2tf(o[j][2]*ih)); vh.y=__uint_as_float(f2tf(o[j][3]*ih));
    *reinterpret_cast<float2*>(olo + col) = vl;
    *reinterpret_cast<float2*>(ohi + col) = vh;
  }
}

// ============ kernel 3: projection, coalesced staging + ldmatrix ===========
// grid (128,8). 8 warps as 4m x 2n; warp 32m x 64n. k-chunk 32, double-buffered.
__global__ void __launch_bounds__(256,2)
proj_kernel(const float* __restrict__ Wt, float* __restrict__ out)
{
  extern __shared__ unsigned sh[];
  unsigned sbase = (unsigned)__cvta_generic_to_shared(sh);
  int tid=threadIdx.x, warp=tid>>5, lane=tid&31, gid=lane>>2, tig=lane&3;
  int mi = lane>>3, lrow = lane&7;
  int r0 = blockIdx.x*128, n0 = blockIdx.y*128;
  int wm = warp>>1, wn = warp&1, m0 = wm*32;

  // A rows for the two m-subtiles
  int arow0 = m0 + (mi&1)*8 + lrow;
  int arow1 = arow0 + 16;
  int asel = mi>>1;
  int browb = wn*64 + (mi>>1)*8 + lrow;
  int bsel = mi&1;

  float acc[2][8][4];
  #pragma unroll
  for (int m=0;m<2;m++)
    #pragma unroll
    for (int j=0;j<8;j++) acc[m][j][0]=acc[m][j][1]=acc[m][j][2]=acc[m][j][3]=0.f;

  auto stage = [&](int kc, int bf){
    #pragma unroll
    for (int i=0;i<4;i++){
      int idx = tid + i*256, row = idx>>3, cv = idx&7;
      uint4 u = *reinterpret_cast<const uint4*>(g_ao + (size_t)(r0+row)*DM + kc*32 + cv*4);
      *reinterpret_cast<uint4*>(&sh[bf*4096 + row*32 + ((cv ^ (row&7))*4)]) = u;
    }
    #pragma unroll
    for (int i=0;i<4;i++){
      int idx = tid + i*256, row = idx>>3, cv = idx&7;
      const float4 v = *reinterpret_cast<const float4*>(g_wt + (size_t)(n0+row)*DM + kc*32 + cv*4);
      uint4 u; u.x=f2tf(v.x); u.y=f2tf(v.y); u.z=f2tf(v.z); u.w=f2tf(v.w);
      *reinterpret_cast<uint4*>(&sh[8192 + bf*4096 + row*32 + ((cv ^ (row&7))*4)]) = u;
    }
  };

  stage(0,0); __syncthreads();
  for (int kc=0; kc<32; kc++){
    int bf = kc&1;
    if (kc<31) stage(kc+1, bf^1);
    unsigned Ab = sbase + bf*16384;
    unsigned Bb = sbase + 32768 + bf*16384;
    #pragma unroll
    for (int k8=0;k8<4;k8++){
      uint4 bb[4];
      #pragma unroll
      for (int jp=0;jp<4;jp++){
        int row = browb + jp*16;
        bb[jp] = ldsm4(Bb + row*128 + (((2*k8+bsel) ^ (row&7))<<4));
      }
      uint4 a0 = ldsm4(Ab + arow0*128 + (((2*k8+asel) ^ (arow0&7))<<4));
      uint4 a1 = ldsm4(Ab + arow1*128 + (((2*k8+asel) ^ (arow1&7))<<4));
      #pragma unroll
      for (int jp=0;jp<4;jp++){
        mma8(acc[0][2*jp],   a0, bb[jp].x, bb[jp].y);
        mma8(acc[0][2*jp+1], a0, bb[jp].z, bb[jp].w);
        mma8(acc[1][2*jp],   a1, bb[jp].x, bb[jp].y);
        mma8(acc[1][2*jp+1], a1, bb[jp].z, bb[jp].w);
      }
    }
    __syncthreads();
  }

  #pragma unroll
  for (int m=0;m<2;m++){
    int rlo = r0 + wm*32 + m*16 + gid, rhi = rlo+8;
    #pragma unroll
    for (int j=0;j<8;j++){
      int col = n0 + wn*64 + j*8 + tig*2;
      *reinterpret_cast<float2*>(out + (size_t)rlo*DM + col) = make_float2(acc[m][j][0], acc[m][j][1]);
      *reinterpret_cast<float2*>(out + (size_t)rhi*DM + col) = make_float2(acc[m][j][2], acc[m][j][3]);
    }
  }
}

extern "C" void kernel_launch(void* const* d_in, const int* in_sizes, int n_in,
                              void* d_out, int out_size)
{
  const float* pre_q = (const float*)d_in[0];
  const float* pre_k = (const float*)d_in[1];
  const float* pre_v = (const float*)d_in[2];
  const float* kker  = (const float*)d_in[3];
  const float* kbias = (const float*)d_in[4];
  const float* vker  = (const float*)d_in[5];
  const float* vbias = (const float*)d_in[6];
  const float* ow    = (const float*)d_in[7];
  float* out = (float*)d_out;

  float *g_kc_p, *g_vc_p, *g_wt_p;
  cudaGetSymbolAddress((void**)&g_kc_p, g_kc);
  cudaGetSymbolAddress((void**)&g_vc_p, g_vc);
  cudaGetSymbolAddress((void**)&g_wt_p, g_wt);

  const int smemC = 24576*4;   // 98304
  const int smemA = 24576*4;   // 98304
  const int smemP = 16384*4;   // 65536
  cudaFuncSetAttribute(compress_kernel, cudaFuncAttributeMaxDynamicSharedMemorySize, smemC);
  cudaFuncSetAttribute(attn_kernel, cudaFuncAttributeMaxDynamicSharedMemorySize, smemA);
  cudaFuncSetAttribute(proj_kernel, cudaFuncAttributeMaxDynamicSharedMemorySize, smemP);

  transpose_w<<<dim3(32,32), 256>>>(ow, g_wt_p);
  compress_kernel<<<512, 256, smemC>>>(pre_k, kker, kbias, g_kc_p, 0);
  compress_kernel<<<512, 256, smemC>>>(pre_v, vker, vbias, g_vc_p, 1);
  attn_kernel<<<dim3(16,128), 256, smemA>>>(pre_q);
  proj_kernel<<<dim3(128,8), 256, smemP>>>(g_wt_p, out);
}

// round 5
// speedup vs baseline: 1.5004x; 1.0121x over previous
#include <cuda_runtime.h>
#include <cstdint>

#define BB 8
#define SS 2048
#define HH 16
#define DD 64
#define DM 1024
#define SC 512

__device__ float g_kc[BB*HH*SC*DD];        // [bh][c][d]
__device__ float g_vc[BB*HH*DD*SC];        // [bh][d][c]  (transposed)
__device__ float g_ao[BB*SS*DM];           // attention out (tf32-rounded bits)
__device__ float g_wt[DM*DM];              // W^T: [n][k]

__device__ __forceinline__ unsigned f2tf(float x){
  unsigned u; asm("cvt.rna.tf32.f32 %0, %1;" : "=r"(u) : "f"(x)); return u;
}
__device__ __forceinline__ void mma8(float* c, uint4 a, unsigned b0, unsigned b1){
  asm volatile(
    "mma.sync.aligned.m16n8k8.row.col.f32.tf32.tf32.f32 "
    "{%0,%1,%2,%3},{%4,%5,%6,%7},{%8,%9},{%0,%1,%2,%3};"
    : "+f"(c[0]), "+f"(c[1]), "+f"(c[2]), "+f"(c[3])
    : "r"(a.x), "r"(a.y), "r"(a.z), "r"(a.w), "r"(b0), "r"(b1));
}
__device__ __forceinline__ uint4 ldsm4(unsigned addr){
  uint4 r;
  asm volatile("ldmatrix.sync.aligned.m8n8.x4.shared.b16 {%0,%1,%2,%3}, [%4];"
    : "=r"(r.x), "=r"(r.y), "=r"(r.z), "=r"(r.w) : "r"(addr));
  return r;
}

// ============ kernel 0: W -> W^T ==========================================
__global__ void __launch_bounds__(256)
transpose_w(const float* __restrict__ W, float* __restrict__ Wt)
{
  __shared__ float t[32][33];
  int bx = blockIdx.x*32, by = blockIdx.y*32;
  int tx = threadIdx.x & 31, ty = threadIdx.x >> 5;
  #pragma unroll
  for (int j=0;j<4;j++)
    t[ty+j*8][tx] = W[(size_t)(by+ty+j*8)*DM + bx+tx];
  __syncthreads();
  #pragma unroll
  for (int j=0;j<4;j++)
    Wt[(size_t)(bx+ty+j*8)*DM + by+tx] = t[tx][ty+j*8];
}

// ============ kernel 1: strided conv (gathered GEMM 128x64, K=256) ========
__global__ void __launch_bounds__(256,2)
compress_kernel(const float* __restrict__ pre, const float* __restrict__ ker,
                const float* __restrict__ bias, float* __restrict__ outc,
                int transposed)
{
  extern __shared__ unsigned sh[];
  unsigned* Af = sh;
  unsigned* Bf = sh + 16384;
  int tid=threadIdx.x, warp=tid>>5, lane=tid&31, gid=lane>>2, tig=lane&3;
  int bh = blockIdx.x>>2, t0 = (blockIdx.x&3)*128;
  int b = bh>>4, h = bh&15;
  const float* base = pre + ((size_t)b*SS*HH + h)*DD;
  int wm = warp>>1, wn = warp&1;

  float acc[2][4][4];
  #pragma unroll
  for (int m=0;m<2;m++)
    #pragma unroll
    for (int j=0;j<4;j++) acc[m][j][0]=acc[m][j][1]=acc[m][j][2]=acc[m][j][3]=0.f;

  auto stage = [&](int w, int bf){
    #pragma unroll
    for (int i=0;i<8;i++){
      int id = warp*8+i, mt = id>>3, k8 = id&7;
      const float* g = base + (size_t)((t0+mt*16+gid)*4 + w)*(HH*DD) + k8*8+tig;
      uint4 u;
      u.x=f2tf(g[0]); u.y=f2tf(g[8*4*HH*DD]); u.z=f2tf(g[4]); u.w=f2tf(g[8*4*HH*DD+4]);
      *reinterpret_cast<uint4*>(&Af[bf*8192 + id*128 + lane*4]) = u;
    }
    #pragma unroll
    for (int i=0;i<4;i++){
      int id = warp*4+i, nt = id>>2, kp = id&3;
      const float* g = ker + w*DD*DD + (kp*16+tig)*DD + nt*8+gid;
      uint4 u;
      u.x=f2tf(g[0]); u.y=f2tf(g[4*DD]); u.z=f2tf(g[8*DD]); u.w=f2tf(g[12*DD]);
      *reinterpret_cast<uint4*>(&Bf[bf*4096 + id*128 + lane*4]) = u;
    }
  };

  stage(0,0); __syncthreads();
  for (int w=0; w<4; w++){
    int bf = w&1;
    if (w<3) stage(w+1, bf^1);
    #pragma unroll
    for (int kp=0;kp<4;kp++){
      uint4 bb[4];
      #pragma unroll
      for (int j=0;j<4;j++)
        bb[j] = *reinterpret_cast<const uint4*>(&Bf[bf*4096 + ((wn*4+j)*4+kp)*128 + lane*4]);
      #pragma unroll
      for (int m=0;m<2;m++){
        uint4 a0 = *reinterpret_cast<const uint4*>(&Af[bf*8192 + ((wm*2+m)*8 + kp*2  )*128 + lane*4]);
        uint4 a1 = *reinterpret_cast<const uint4*>(&Af[bf*8192 + ((wm*2+m)*8 + kp*2+1)*128 + lane*4]);
        #pragma unroll
        for (int j=0;j<4;j++){
          mma8(acc[m][j], a0, bb[j].x, bb[j].y);
          mma8(acc[m][j], a1, bb[j].z, bb[j].w);
        }
      }
    }
    __syncthreads();
  }

  #pragma unroll
  for (int m=0;m<2;m++){
    int rlo = t0 + wm*32 + m*16 + gid, rhi = rlo+8;
    #pragma unroll
    for (int j=0;j<4;j++){
      int col = wn*32 + j*8 + tig*2;
      float b0 = bias[col], b1 = bias[col+1];
      float v00=__uint_as_float(f2tf(acc[m][j][0]+b0));
      float v01=__uint_as_float(f2tf(acc[m][j][1]+b1));
      float v10=__uint_as_float(f2tf(acc[m][j][2]+b0));
      float v11=__uint_as_float(f2tf(acc[m][j][3]+b1));
      if (!transposed){
        *reinterpret_cast<float2*>(outc + ((size_t)bh*SC+rlo)*DD + col) = make_float2(v00,v01);
        *reinterpret_cast<float2*>(outc + ((size_t)bh*SC+rhi)*DD + col) = make_float2(v10,v11);
      } else {
        float* o0 = outc + ((size_t)bh*DD + col)*SC;
        float* o1 = outc + ((size_t)bh*DD + col+1)*SC;
        o0[rlo]=v00; o1[rlo]=v01; o0[rhi]=v10; o1[rhi]=v11;
      }
    }
  }
}

// ============ kernel 2: flash attention, 32q per warp, 256q per block ======
// grid (8,128). B-fragment ldmatrix reused across 2 m-subtiles.
__global__ void __launch_bounds__(256,1)
attn_kernel(const float* __restrict__ preq)
{
  extern __shared__ unsigned sh[];
  // words: K[2][4096] @0, V[2][4096] @8192, Pf[8 warps][2048] @16384
  unsigned sbase = (unsigned)__cvta_generic_to_shared(sh);
  unsigned* Pf = sh + 16384;

  int tid=threadIdx.x, warp=tid>>5, lane=tid&31, gid=lane>>2, tig=lane&3;
  int mi = lane>>3, lrow = lane&7;
  int bh = blockIdx.y, b = bh>>4, h = bh&15;
  int q0 = blockIdx.x*256, m0 = warp*32;
  const float* qb = preq + ((size_t)b*SS*HH + h)*DD;
  const float* kb = g_kc + (size_t)bh*SC*DD;
  const float* vb = g_vc + (size_t)bh*DD*SC;

  // Q fragments -> registers, 2 m-subtiles
  uint4 q[2][8];
  #pragma unroll
  for (int mt=0; mt<2; mt++){
    const float* qr = qb + (size_t)(q0+m0+mt*16+gid)*(HH*DD) + tig;
    #pragma unroll
    for (int k8=0;k8<8;k8++){
      q[mt][k8].x = f2tf(qr[k8*8]);
      q[mt][k8].y = f2tf(qr[8*HH*DD + k8*8]);
      q[mt][k8].z = f2tf(qr[k8*8+4]);
      q[mt][k8].w = f2tf(qr[8*HH*DD + k8*8+4]);
    }
  }

  int browb = (mi>>1)*8 + lrow;
  int bsel = mi&1;

  float o[2][8][4];
  #pragma unroll
  for (int mt=0;mt<2;mt++)
    #pragma unroll
    for (int j=0;j<8;j++) o[mt][j][0]=o[mt][j][1]=o[mt][j][2]=o[mt][j][3]=0.f;
  float mS[2][2] = {{-1e30f,-1e30f},{-1e30f,-1e30f}};
  float lS[2][2] = {{0.f,0.f},{0.f,0.f}};
  const float scale = 0.125f;

  auto stage = [&](int ch, int bf){
    int c0 = ch*64;
    #pragma unroll
    for (int i=0;i<4;i++){
      int idx = tid + i*256, row = idx>>4, cv = idx&15;
      uint4 kv = *reinterpret_cast<const uint4*>(kb + (size_t)(c0+row)*DD + cv*4);
      *reinterpret_cast<uint4*>(&sh[bf*4096 + row*64 + ((cv ^ (row&7))*4)]) = kv;
      uint4 vv = *reinterpret_cast<const uint4*>(vb + (size_t)row*SC + c0 + cv*4);
      *reinterpret_cast<uint4*>(&sh[8192 + bf*4096 + row*64 + ((cv ^ (row&7))*4)]) = vv;
    }
  };

  stage(0,0); __syncthreads();

  for (int ch=0; ch<8; ch++){
    int bf = ch&1;
    if (ch<7) stage(ch+1, bf^1);
    unsigned Kb = sbase + bf*16384;
    unsigned Vb = sbase + 32768 + bf*16384;

    // S = Q K^T for both m-subtiles; each B ldmatrix serves 4 mmas
    float s[2][8][4];
    #pragma unroll
    for (int mt=0;mt<2;mt++)
      #pragma unroll
      for (int j=0;j<8;j++) s[mt][j][0]=s[mt][j][1]=s[mt][j][2]=s[mt][j][3]=0.f;
    #pragma unroll
    for (int k8=0;k8<8;k8++){
      #pragma unroll
      for (int jp=0;jp<4;jp++){
        int row = jp*16 + browb;
        uint4 bb = ldsm4(Kb + row*256 + (((2*k8+bsel) ^ (row&7))<<4));
        mma8(s[0][2*jp],   q[0][k8], bb.x, bb.y);
        mma8(s[0][2*jp+1], q[0][k8], bb.z, bb.w);
        mma8(s[1][2*jp],   q[1][k8], bb.x, bb.y);
        mma8(s[1][2*jp+1], q[1][k8], bb.z, bb.w);
      }
    }

    // softmax per m-subtile
    #pragma unroll
    for (int mt=0;mt<2;mt++){
      float mx_lo=-1e30f, mx_hi=-1e30f;
      #pragma unroll
      for (int j=0;j<8;j++){
        s[mt][j][0]*=scale; s[mt][j][1]*=scale; s[mt][j][2]*=scale; s[mt][j][3]*=scale;
        mx_lo = fmaxf(mx_lo, fmaxf(s[mt][j][0], s[mt][j][1]));
        mx_hi = fmaxf(mx_hi, fmaxf(s[mt][j][2], s[mt][j][3]));
      }
      mx_lo = fmaxf(mx_lo, __shfl_xor_sync(~0u, mx_lo, 1));
      mx_lo = fmaxf(mx_lo, __shfl_xor_sync(~0u, mx_lo, 2));
      mx_hi = fmaxf(mx_hi, __shfl_xor_sync(~0u, mx_hi, 1));
      mx_hi = fmaxf(mx_hi, __shfl_xor_sync(~0u, mx_hi, 2));
      float mn_lo = fmaxf(mS[mt][0], mx_lo), mn_hi = fmaxf(mS[mt][1], mx_hi);
      float al = __expf(mS[mt][0]-mn_lo), ah = __expf(mS[mt][1]-mn_hi);
      float rl = 0.f, rh = 0.f;
      int t0p = (tig*2)&3, t1p = (tig*2+1)&3, kk = tig>>1;
      #pragma unroll
      for (int j=0;j<8;j++){
        float p0=__expf(s[mt][j][0]-mn_lo), p1=__expf(s[mt][j][1]-mn_lo);
        float p2=__expf(s[mt][j][2]-mn_hi), p3=__expf(s[mt][j][3]-mn_hi);
        rl += p0+p1; rh += p2+p3;
        unsigned bj = warp*2048 + mt*1024 + j*128;
        Pf[bj + (gid*4+t0p)*4 + 2*kk    ] = f2tf(p0);
        Pf[bj + (gid*4+t1p)*4 + 2*kk    ] = f2tf(p1);
        Pf[bj + (gid*4+t0p)*4 + 2*kk + 1] = f2tf(p2);
        Pf[bj + (gid*4+t1p)*4 + 2*kk + 1] = f2tf(p3);
      }
      rl += __shfl_xor_sync(~0u, rl, 1); rl += __shfl_xor_sync(~0u, rl, 2);
      rh += __shfl_xor_sync(~0u, rh, 1); rh += __shfl_xor_sync(~0u, rh, 2);
      lS[mt][0] = lS[mt][0]*al + rl; lS[mt][1] = lS[mt][1]*ah + rh;
      mS[mt][0] = mn_lo; mS[mt][1] = mn_hi;
      #pragma unroll
      for (int j=0;j<8;j++){
        o[mt][j][0]*=al; o[mt][j][1]*=al; o[mt][j][2]*=ah; o[mt][j][3]*=ah;
      }
    }
    __syncwarp();

    // O += P V ; V ldmatrix reused across 2 m-subtiles
    #pragma unroll
    for (int k8=0;k8<8;k8++){
      uint4 a0 = *reinterpret_cast<const uint4*>(&Pf[warp*2048 +        k8*128 + lane*4]);
      uint4 a1 = *reinterpret_cast<const uint4*>(&Pf[warp*2048 + 1024 + k8*128 + lane*4]);
      #pragma unroll
      for (int jp=0;jp<4;jp++){
        int row = jp*16 + browb;
        uint4 vv = ldsm4(Vb + row*256 + (((2*k8+bsel) ^ (row&7))<<4));
        mma8(o[0][2*jp],   a0, vv.x, vv.y);
        mma8(o[0][2*jp+1], a0, vv.z, vv.w);
        mma8(o[1][2*jp],   a1, vv.x, vv.y);
        mma8(o[1][2*jp+1], a1, vv.z, vv.w);
      }
    }
    __syncthreads();
  }

  #pragma unroll
  for (int mt=0;mt<2;mt++){
    float il = 1.f/lS[mt][0], ih = 1.f/lS[mt][1];
    int qlo = q0+m0+mt*16+gid, qhi = qlo+8;
    float* olo = g_ao + ((size_t)(b*SS+qlo)*HH + h)*DD;
    float* ohi = g_ao + ((size_t)(b*SS+qhi)*HH + h)*DD;
    #pragma unroll
    for (int j=0;j<8;j++){
      int col = j*8 + tig*2;
      float2 vl, vh;
      vl.x=__uint_as_float(f2tf(o[mt][j][0]*il)); vl.y=__uint_as_float(f2tf(o[mt][j][1]*il));
      vh.x=__uint_as_float(f2tf(o[mt][j][2]*ih)); vh.y=__uint_as_float(f2tf(o[mt][j][3]*ih));
      *reinterpret_cast<float2*>(olo + col) = vl;
      *reinterpret_cast<float2*>(ohi + col) = vh;
    }
  }
}

// ============ kernel 3: projection, coalesced staging + ldmatrix ===========
__global__ void __launch_bounds__(256,2)
proj_kernel(const float* __restrict__ Wt, float* __restrict__ out)
{
  extern __shared__ unsigned sh[];
  unsigned sbase = (unsigned)__cvta_generic_to_shared(sh);
  int tid=threadIdx.x, warp=tid>>5, lane=tid&31, gid=lane>>2, tig=lane&3;
  int mi = lane>>3, lrow = lane&7;
  int r0 = blockIdx.x*128, n0 = blockIdx.y*128;
  int wm = warp>>1, wn = warp&1, m0 = wm*32;

  int arow0 = m0 + (mi&1)*8 + lrow;
  int arow1 = arow0 + 16;
  int asel = mi>>1;
  int browb = wn*64 + (mi>>1)*8 + lrow;
  int bsel = mi&1;

  float acc[2][8][4];
  #pragma unroll
  for (int m=0;m<2;m++)
    #pragma unroll
    for (int j=0;j<8;j++) acc[m][j][0]=acc[m][j][1]=acc[m][j][2]=acc[m][j][3]=0.f;

  auto stage = [&](int kc, int bf){
    #pragma unroll
    for (int i=0;i<4;i++){
      int idx = tid + i*256, row = idx>>3, cv = idx&7;
      uint4 u = *reinterpret_cast<const uint4*>(g_ao + (size_t)(r0+row)*DM + kc*32 + cv*4);
      *reinterpret_cast<uint4*>(&sh[bf*4096 + row*32 + ((cv ^ (row&7))*4)]) = u;
    }
    #pragma unroll
    for (int i=0;i<4;i++){
      int idx = tid + i*256, row = idx>>3, cv = idx&7;
      const float4 v = *reinterpret_cast<const float4*>(g_wt + (size_t)(n0+row)*DM + kc*32 + cv*4);
      uint4 u; u.x=f2tf(v.x); u.y=f2tf(v.y); u.z=f2tf(v.z); u.w=f2tf(v.w);
      *reinterpret_cast<uint4*>(&sh[8192 + bf*4096 + row*32 + ((cv ^ (row&7))*4)]) = u;
    }
  };

  stage(0,0); __syncthreads();
  for (int kc=0; kc<32; kc++){
    int bf = kc&1;
    if (kc<31) stage(kc+1, bf^1);
    unsigned Ab = sbase + bf*16384;
    unsigned Bb = sbase + 32768 + bf*16384;
    #pragma unroll
    for (int k8=0;k8<4;k8++){
      uint4 bb[4];
      #pragma unroll
      for (int jp=0;jp<4;jp++){
        int row = browb + jp*16;
        bb[jp] = ldsm4(Bb + row*128 + (((2*k8+bsel) ^ (row&7))<<4));
      }
      uint4 a0 = ldsm4(Ab + arow0*128 + (((2*k8+asel) ^ (arow0&7))<<4));
      uint4 a1 = ldsm4(Ab + arow1*128 + (((2*k8+asel) ^ (arow1&7))<<4));
      #pragma unroll
      for (int jp=0;jp<4;jp++){
        mma8(acc[0][2*jp],   a0, bb[jp].x, bb[jp].y);
        mma8(acc[0][2*jp+1], a0, bb[jp].z, bb[jp].w);
        mma8(acc[1][2*jp],   a1, bb[jp].x, bb[jp].y);
        mma8(acc[1][2*jp+1], a1, bb[jp].z, bb[jp].w);
      }
    }
    __syncthreads();
  }

  #pragma unroll
  for (int m=0;m<2;m++){
    int rlo = r0 + wm*32 + m*16 + gid, rhi = rlo+8;
    #pragma unroll
    for (int j=0;j<8;j++){
      int col = n0 + wn*64 + j*8 + tig*2;
      *reinterpret_cast<float2*>(out + (size_t)rlo*DM + col) = make_float2(acc[m][j][0], acc[m][j][1]);
      *reinterpret_cast<float2*>(out + (size_t)rhi*DM + col) = make_float2(acc[m][j][2], acc[m][j][3]);
    }
  }
}

extern "C" void kernel_launch(void* const* d_in, const int* in_sizes, int n_in,
                              void* d_out, int out_size)
{
  const float* pre_q = (const float*)d_in[0];
  const float* pre_k = (const float*)d_in[1];
  const float* pre_v = (const float*)d_in[2];
  const float* kker  = (const float*)d_in[3];
  const float* kbias = (const float*)d_in[4];
  const float* vker  = (const float*)d_in[5];
  const float* vbias = (const float*)d_in[6];
  const float* ow    = (const float*)d_in[7];
  float* out = (float*)d_out;

  float *g_kc_p, *g_vc_p, *g_wt_p;
  cudaGetSymbolAddress((void**)&g_kc_p, g_kc);
  cudaGetSymbolAddress((void**)&g_vc_p, g_vc);
  cudaGetSymbolAddress((void**)&g_wt_p, g_wt);

  const int smemC = 24576*4;   // 98304
  const int smemA = 32768*4;   // 131072
  const int smemP = 16384*4;   // 65536
  cudaFuncSetAttribute(compress_kernel, cudaFuncAttributeMaxDynamicSharedMemorySize, smemC);
  cudaFuncSetAttribute(attn_kernel, cudaFuncAttributeMaxDynamicSharedMemorySize, smemA);
  cudaFuncSetAttribute(proj_kernel, cudaFuncAttributeMaxDynamicSharedMemorySize, smemP);

  transpose_w<<<dim3(32,32), 256>>>(ow, g_wt_p);
  compress_kernel<<<512, 256, smemC>>>(pre_k, kker, kbias, g_kc_p, 0);
  compress_kernel<<<512, 256, smemC>>>(pre_v, vker, vbias, g_vc_p, 1);
  attn_kernel<<<dim3(8,128), 256, smemA>>>(pre_q);
  proj_kernel<<<dim3(128,8), 256, smemP>>>(g_wt_p, out);
}